// round 9
// baseline (speedup 1.0000x reference)
#include <cuda_runtime.h>
#include <cuda_fp16.h>
#include <math.h>

#define B 4
#define C 64
#define IC 16
#define H 128
#define W 128
#define N 4096
#define BN_COUNT (B*H*W)
#define SPLITK 4
#define LOG2E 1.44269504088896340736f

// ------------------------- scratch -------------------------
__device__ __half g_qh[B * N * IC];        // Q (theta * log2e)  [n][d]
__device__ __half g_kh[B * N * IC];        // K (phi)            [n][d]
__device__ __half g_vth[B * IC * N];       // V transposed       [b][d][n]
__device__ float g_opart[SPLITK * B * N * IC];
__device__ float g_lpart[SPLITK * B * N];
__device__ float g_mpart[SPLITK * B * N];
__device__ float g_y[B * N * IC];
__device__ float g_z[B * C * H * W];
__device__ float g_bnpart[B * C * 4 * 2];
__device__ float g_bnstat[C * 2];

__device__ __forceinline__ float ex2a(float f) {
    float r; asm("ex2.approx.ftz.f32 %0,%1;" : "=f"(r) : "f"(f)); return r;
}
__device__ __forceinline__ unsigned pack2(float a, float b) {
    __half2 h = __floats2half2_rn(a, b);
    return *(unsigned*)&h;
}
// D = A*B + C (accumulate into d)
__device__ __forceinline__ void mma_f16(float* d, unsigned a0, unsigned a1, unsigned a2, unsigned a3,
                                        unsigned b0, unsigned b1) {
    asm("mma.sync.aligned.m16n8k16.row.col.f32.f16.f16.f32 "
        "{%0,%1,%2,%3},{%4,%5,%6,%7},{%8,%9},{%0,%1,%2,%3};"
        : "+f"(d[0]), "+f"(d[1]), "+f"(d[2]), "+f"(d[3])
        : "r"(a0), "r"(a1), "r"(a2), "r"(a3), "r"(b0), "r"(b1));
}
// D = A*B (zero C, no accumulate-read)
__device__ __forceinline__ void mma_f16_zc(float* d, unsigned a0, unsigned a1, unsigned a2, unsigned a3,
                                           unsigned b0, unsigned b1) {
    asm("mma.sync.aligned.m16n8k16.row.col.f32.f16.f16.f32 "
        "{%0,%1,%2,%3},{%4,%5,%6,%7},{%8,%9},{%10,%11,%12,%13};"
        : "=f"(d[0]), "=f"(d[1]), "=f"(d[2]), "=f"(d[3])
        : "r"(a0), "r"(a1), "r"(a2), "r"(a3), "r"(b0), "r"(b1),
          "f"(0.f), "f"(0.f), "f"(0.f), "f"(0.f));
}

// ------------------- K1: downsample (odd-pixel subsample) + QKV (fp16 out) -------------------
// jax scale_and_translate, scale=0.5, trans=-0.25 => sample_f = 2*o+1 (exact hit)
__global__ void __launch_bounds__(256) k_down_proj(
    const float* __restrict__ x,
    const float* __restrict__ gw,  const float* __restrict__ gb,
    const float* __restrict__ thw, const float* __restrict__ thb,
    const float* __restrict__ phw, const float* __restrict__ phb)
{
    __shared__ float xd[64][68];
    __shared__ float Wm[48][64];
    __shared__ float Bm[48];
    __shared__ __half qks[2][64][16];

    int b  = blockIdx.x >> 6;
    int oi = blockIdx.x & 63;
    int t  = threadIdx.x;  // 256

    for (int idx = t; idx < 16 * 64; idx += 256) {
        Wm[idx >> 6][idx & 63]        = thw[idx] * LOG2E;
        Wm[16 + (idx >> 6)][idx & 63] = phw[idx];
        Wm[32 + (idx >> 6)][idx & 63] = gw[idx];
    }
    if (t < 16) { Bm[t] = thb[t] * LOG2E; Bm[16 + t] = phb[t]; Bm[32 + t] = gb[t]; }

    for (int idx = t; idx < 4096; idx += 256) {
        int c = idx >> 6, p = idx & 63;
        xd[p][c] = x[(((size_t)b * C + c) * H + 2 * oi + 1) * W + 2 * p + 1];
    }
    __syncthreads();

    int p   = t & 63;
    int grp = t >> 6;

    float xv[64];
    #pragma unroll
    for (int k = 0; k < 16; k++) *(float4*)&xv[4 * k] = *(float4*)&xd[p][4 * k];

    int base_n = b * N + oi * 64;
    #pragma unroll
    for (int j = 0; j < 12; j++) {
        int o = grp * 12 + j;
        float s0 = 0.f, s1 = 0.f, s2 = 0.f, s3 = 0.f;
        #pragma unroll
        for (int k = 0; k < 16; k++) {
            float4 wv = *(float4*)&Wm[o][4 * k];
            s0 += wv.x * xv[4 * k];
            s1 += wv.y * xv[4 * k + 1];
            s2 += wv.z * xv[4 * k + 2];
            s3 += wv.w * xv[4 * k + 3];
        }
        float s = Bm[o] + ((s0 + s1) + (s2 + s3));
        int which = o >> 4, oo = o & 15;
        if (which < 2) qks[which][p][oo] = __float2half_rn(s);
        else           g_vth[((size_t)b * IC + oo) * N + oi * 64 + p] = __float2half_rn(s);
    }
    __syncthreads();

    for (int idx = t; idx < 1024; idx += 256) {
        int which = idx >> 9;
        int rest  = idx & 511;
        int pp = rest >> 3, u = rest & 7;
        unsigned v = *(unsigned*)&qks[which][pp][u * 2];
        __half* dst = which ? g_kh : g_qh;
        *((unsigned*)dst + (size_t)(base_n + pp) * 8 + u) = v;
    }
}

// ------------------- K2: fp16 mma flash attention, h2exp2, l-via-ones-column -------------------
#define KT 32
#define KPC (N / SPLITK)
__global__ void __launch_bounds__(128) k_attn()
{
    __shared__ __half Ks[KT][24];    // [key][d] pad 24
    __shared__ __half Vt[24][40];    // [d][key] pad 40; rows 16..23: ones column + zeros

    int b    = blockIdx.x >> 8;
    int qt   = (blockIdx.x >> 2) & 63;
    int part = blockIdx.x & 3;
    int t    = threadIdx.x;
    int wp   = t >> 5;
    int lane = t & 31;
    int g    = lane >> 2;
    int t4   = lane & 3;

    int q0 = b * N + qt * 64 + wp * 16;

    unsigned qa0 = *(const unsigned*)(g_qh + (size_t)(q0 + g)     * IC + 2 * t4);
    unsigned qa1 = *(const unsigned*)(g_qh + (size_t)(q0 + g + 8) * IC + 2 * t4);
    unsigned qa2 = *(const unsigned*)(g_qh + (size_t)(q0 + g)     * IC + 2 * t4 + 8);
    unsigned qa3 = *(const unsigned*)(g_qh + (size_t)(q0 + g + 8) * IC + 2 * t4 + 8);

    // od[0..1]: PV accumulators (d chunks). od[2]: l lane (ones column).
    float od[3][4];
    #pragma unroll
    for (int c = 0; c < 3; c++)
        #pragma unroll
        for (int i = 0; i < 4; i++) od[c][i] = 0.f;
    float m0 = -1e30f, m1 = -1e30f;

    // init Vt rows 16..23: row16 = 1, rows 17..23 = 0
    for (int idx = t; idx < 8 * 40; idx += 128) {
        int r = idx / 40, cc = idx - r * 40;
        Vt[16 + r][cc] = (r == 0) ? __float2half(1.f) : __float2half(0.f);
    }

    int koff = part * KPC;
    for (int kt = 0; kt < KPC; kt += KT) {
        {
            int key = t >> 2, seg = t & 3;
            *(uint2*)&Ks[key][seg * 4] =
                *(const uint2*)(g_kh + ((size_t)(b * N + koff + kt) + key) * IC + seg * 4);
            int d = t >> 3, seg8 = t & 7;
            *(uint2*)&Vt[d][seg8 * 4] =
                *(const uint2*)(g_vth + ((size_t)b * IC + d) * N + koff + kt + seg8 * 4);
        }
        __syncthreads();

        // S = Q K^T (4 key-chunks of 8), zero-C mma
        float p[4][4];
        #pragma unroll
        for (int c = 0; c < 4; c++) {
            unsigned kb0 = *(const unsigned*)&Ks[c * 8 + g][2 * t4];
            unsigned kb1 = *(const unsigned*)&Ks[c * 8 + g][2 * t4 + 8];
            mma_f16_zc(p[c], qa0, qa1, qa2, qa3, kb0, kb1);
        }

        // tile max per row
        float tm0 = fmaxf(fmaxf(fmaxf(p[0][0], p[0][1]), fmaxf(p[1][0], p[1][1])),
                          fmaxf(fmaxf(p[2][0], p[2][1]), fmaxf(p[3][0], p[3][1])));
        float tm1 = fmaxf(fmaxf(fmaxf(p[0][2], p[0][3]), fmaxf(p[1][2], p[1][3])),
                          fmaxf(fmaxf(p[2][2], p[2][3]), fmaxf(p[3][2], p[3][3])));
        tm0 = fmaxf(tm0, __shfl_xor_sync(0xffffffffu, tm0, 1));
        tm0 = fmaxf(tm0, __shfl_xor_sync(0xffffffffu, tm0, 2));
        tm1 = fmaxf(tm1, __shfl_xor_sync(0xffffffffu, tm1, 1));
        tm1 = fmaxf(tm1, __shfl_xor_sync(0xffffffffu, tm1, 2));

        bool need = (tm0 > m0) || (tm1 > m1);
        if (__any_sync(0xffffffffu, need)) {          // warp-uniform, rarely taken late
            float mn0 = fmaxf(m0, tm0), mn1 = fmaxf(m1, tm1);
            float f0 = ex2a(m0 - mn0), f1 = ex2a(m1 - mn1);
            m0 = mn0; m1 = mn1;
            #pragma unroll
            for (int c = 0; c < 3; c++) {
                od[c][0] *= f0; od[c][1] *= f0;
                od[c][2] *= f1; od[c][3] *= f1;
            }
        }

        // p = exp2(s - m) via f16x2 MUFU; output pairs are directly PV A-fragments
        unsigned pp0[4], pp1[4];
        #pragma unroll
        for (int c = 0; c < 4; c++) {
            unsigned u0 = pack2(p[c][0] - m0, p[c][1] - m0);
            unsigned u1 = pack2(p[c][2] - m1, p[c][3] - m1);
            __half2 e0 = h2exp2(*(__half2*)&u0);
            __half2 e1 = h2exp2(*(__half2*)&u1);
            pp0[c] = *(unsigned*)&e0;
            pp1[c] = *(unsigned*)&e1;
        }

        // PV (+ ones column -> l): 2 key-steps x 3 n-chunks
        #pragma unroll
        for (int s = 0; s < 2; s++) {
            unsigned a0 = pp0[2 * s], a1 = pp1[2 * s], a2 = pp0[2 * s + 1], a3 = pp1[2 * s + 1];
            #pragma unroll
            for (int nc = 0; nc < 3; nc++) {
                unsigned vb0 = *(const unsigned*)&Vt[nc * 8 + g][s * 16 + 2 * t4];
                unsigned vb1 = *(const unsigned*)&Vt[nc * 8 + g][s * 16 + 2 * t4 + 8];
                mma_f16(od[nc], a0, a1, a2, a3, vb0, vb1);
            }
        }
        __syncthreads();
    }

    // l lives in ones-column output: D[row][16] held by t4==0
    if (t4 == 0) {
        size_t base = (size_t)part * (B * N);
        g_lpart[base + q0 + g]     = od[2][0];
        g_lpart[base + q0 + g + 8] = od[2][2];
        g_mpart[base + q0 + g]     = m0;
        g_mpart[base + q0 + g + 8] = m1;
    }

    float* Ob = g_opart + (size_t)part * (B * N) * IC;
    #pragma unroll
    for (int nc = 0; nc < 2; nc++) {
        *(float2*)&Ob[(size_t)(q0 + g)     * IC + nc * 8 + 2 * t4] = make_float2(od[nc][0], od[nc][1]);
        *(float2*)&Ob[(size_t)(q0 + g + 8) * IC + nc * 8 + 2 * t4] = make_float2(od[nc][2], od[nc][3]);
    }
}

// ------------------- K2b: merge split-K partials (max rescale) -------------------
__global__ void k_merge()
{
    int n = blockIdx.x * 256 + threadIdx.x;
    if (n >= B * N) return;
    float m[SPLITK], sc[SPLITK];
    float M = -1e30f;
    #pragma unroll
    for (int p = 0; p < SPLITK; p++) { m[p] = g_mpart[(size_t)p * (B * N) + n]; M = fmaxf(M, m[p]); }
    float l = 0.f;
    #pragma unroll
    for (int p = 0; p < SPLITK; p++) {
        sc[p] = ex2a(m[p] - M);
        l += g_lpart[(size_t)p * (B * N) + n] * sc[p];
    }
    float inv = 1.f / l;
    float acc[16];
    #pragma unroll
    for (int i = 0; i < 16; i++) acc[i] = 0.f;
    #pragma unroll
    for (int p = 0; p < SPLITK; p++) {
        const float4* a = (const float4*)(g_opart + ((size_t)p * (B * N) + n) * IC);
        #pragma unroll
        for (int i = 0; i < 4; i++) {
            float4 v = a[i];
            acc[i * 4 + 0] += v.x * sc[p]; acc[i * 4 + 1] += v.y * sc[p];
            acc[i * 4 + 2] += v.z * sc[p]; acc[i * 4 + 3] += v.w * sc[p];
        }
    }
    float4* y = (float4*)(g_y + (size_t)n * IC);
    #pragma unroll
    for (int i = 0; i < 4; i++) {
        float4 r;
        r.x = acc[i * 4 + 0] * inv; r.y = acc[i * 4 + 1] * inv;
        r.z = acc[i * 4 + 2] * inv; r.w = acc[i * 4 + 3] * inv;
        y[i] = r;
    }
}

// ------------------- K3: upsample + out conv + residual (unrolled channel loop) -------------------
// jax scale_and_translate, scale=2, trans=+0.5 => sample_f = 0.5*o - 0.5 (clamped taps)
__global__ void __launch_bounds__(256) k_out(const float* __restrict__ x,
                                             const float* __restrict__ ow,
                                             const float* __restrict__ ob)
{
    __shared__ float yr[16][65];
    __shared__ float Wo[64][16];
    __shared__ float obs[64];

    int b = blockIdx.x >> 7;
    int h = blockIdx.x & 127;
    int t = threadIdx.x;  // 256

    for (int idx = t; idx < 1024; idx += 256) Wo[idx >> 4][idx & 15] = ow[idx];
    if (t < 64) obs[t] = ob[t];

    float fh = 0.5f * (float)h - 0.5f;
    int   ihf = (int)floorf(fh);
    float w1  = fh - (float)ihf;
    int ih0 = ihf < 0 ? 0 : ihf;
    int ih1 = (ihf + 1) > 63 ? 63 : (ihf + 1);

    for (int idx = t; idx < 1024; idx += 256) {
        int i = idx & 15, jw = idx >> 4;
        float a = g_y[((size_t)b * N + ih0 * 64 + jw) * IC + i];
        float c = g_y[((size_t)b * N + ih1 * 64 + jw) * IC + i];
        yr[i][jw] = (1.f - w1) * a + w1 * c;
    }
    __syncthreads();

    int w    = t & 127;
    int half = t >> 7;

    float fw = 0.5f * (float)w - 0.5f;
    int   jf = (int)floorf(fw);
    float ww = fw - (float)jf;
    int j0 = jf < 0 ? 0 : jf;
    int j1 = (jf + 1) > 63 ? 63 : (jf + 1);

    float yv[16];
    #pragma unroll
    for (int i = 0; i < 16; i++)
        yv[i] = (1.f - ww) * yr[i][j0] + ww * yr[i][j1];

    const float* xrow = x   + ((size_t)b * C * H + h) * W;
    float*       zrow = g_z + ((size_t)b * C * H + h) * W;

    #pragma unroll
    for (int ci = 0; ci < 32; ci++) {
        int c = half + 2 * ci;
        float4 w0 = *(float4*)&Wo[c][0];
        float4 w4 = *(float4*)&Wo[c][4];
        float4 w8 = *(float4*)&Wo[c][8];
        float4 wc = *(float4*)&Wo[c][12];
        float s = obs[c];
        s += w0.x * yv[0]  + w0.y * yv[1]  + w0.z * yv[2]  + w0.w * yv[3];
        s += w4.x * yv[4]  + w4.y * yv[5]  + w4.z * yv[6]  + w4.w * yv[7];
        s += w8.x * yv[8]  + w8.y * yv[9]  + w8.z * yv[10] + w8.w * yv[11];
        s += wc.x * yv[12] + wc.y * yv[13] + wc.z * yv[14] + wc.w * yv[15];
        zrow[(size_t)c * (H * W) + w] = xrow[(size_t)c * (H * W) + w] + s;
    }
}

// ------------------- K3b: BN partial reduction over g_z (deterministic) -------------------
__global__ void k_bnred()
{
    __shared__ float ss[8], sq[8];
    int plane = blockIdx.x >> 2;
    int chunk = blockIdx.x & 3;
    int t = threadIdx.x;

    const float4* p = (const float4*)(g_z + (size_t)plane * (H * W) + chunk * 4096);
    float s = 0.f, q = 0.f;
    #pragma unroll
    for (int i = 0; i < 4; i++) {
        float4 v = p[i * 256 + t];
        s += ((v.x + v.y) + (v.z + v.w));
        q += ((v.x * v.x + v.y * v.y) + (v.z * v.z + v.w * v.w));
    }
    #pragma unroll
    for (int off = 16; off; off >>= 1) {
        s += __shfl_down_sync(0xffffffffu, s, off);
        q += __shfl_down_sync(0xffffffffu, q, off);
    }
    int warp = t >> 5, lane = t & 31;
    if (lane == 0) { ss[warp] = s; sq[warp] = q; }
    __syncthreads();
    if (t == 0) {
        float S = ((ss[0] + ss[1]) + (ss[2] + ss[3])) + ((ss[4] + ss[5]) + (ss[6] + ss[7]));
        float Q = ((sq[0] + sq[1]) + (sq[2] + sq[3])) + ((sq[4] + sq[5]) + (sq[6] + sq[7]));
        g_bnpart[((size_t)plane * 4 + chunk) * 2 + 0] = S;
        g_bnpart[((size_t)plane * 4 + chunk) * 2 + 1] = Q;
    }
}

// ------------------- K4: finalize BN stats -------------------
__global__ void k_stats()
{
    int c = threadIdx.x;
    if (c >= C) return;
    float s = 0.f, q = 0.f;
    #pragma unroll
    for (int b = 0; b < B; b++)
        #pragma unroll
        for (int ch = 0; ch < 4; ch++) {
            size_t idx = (((size_t)b * C + c) * 4 + ch) * 2;
            s += g_bnpart[idx + 0];
            q += g_bnpart[idx + 1];
        }
    float mean = s * (1.f / (float)BN_COUNT);
    float var  = q * (1.f / (float)BN_COUNT) - mean * mean;
    g_bnstat[c * 2 + 0] = mean;
    g_bnstat[c * 2 + 1] = rsqrtf(var + 1e-5f);
}

// ------------------- K5: normalize -------------------
__global__ void k_norm(const float* __restrict__ gamma, const float* __restrict__ beta,
                       float* __restrict__ out)
{
    size_t i4 = (size_t)blockIdx.x * 256 + threadIdx.x;
    int c = (int)((i4 >> 12) & 63);
    float mean = g_bnstat[c * 2 + 0];
    float rstd = g_bnstat[c * 2 + 1];
    float ga = gamma[c] * rstd;
    float be = beta[c] - mean * ga;
    float4 z = ((const float4*)g_z)[i4];
    float4 r;
    r.x = z.x * ga + be; r.y = z.y * ga + be;
    r.z = z.z * ga + be; r.w = z.w * ga + be;
    ((float4*)out)[i4] = r;
}

// ------------------------------- launch -------------------------------
extern "C" void kernel_launch(void* const* d_in, const int* in_sizes, int n_in,
                              void* d_out, int out_size)
{
    const float* x     = (const float*)d_in[0];
    const float* g_w   = (const float*)d_in[1];
    const float* g_b   = (const float*)d_in[2];
    const float* th_w  = (const float*)d_in[3];
    const float* th_b  = (const float*)d_in[4];
    const float* ph_w  = (const float*)d_in[5];
    const float* ph_b  = (const float*)d_in[6];
    const float* out_w = (const float*)d_in[7];
    const float* out_b = (const float*)d_in[8];
    const float* gamma = (const float*)d_in[9];
    const float* beta  = (const float*)d_in[10];
    float* out = (float*)d_out;

    k_down_proj<<<B * 64, 256>>>(x, g_w, g_b, th_w, th_b, ph_w, ph_b);
    k_attn<<<B * 64 * SPLITK, 128>>>();
    k_merge<<<64, 256>>>();
    k_out<<<B * H, 256>>>(x, out_w, out_b);
    k_bnred<<<B * C * 4, 256>>>();
    k_stats<<<1, 64>>>();
    k_norm<<<4096, 256>>>(gamma, beta, out);
}

// round 10
// speedup vs baseline: 1.0427x; 1.0427x over previous
#include <cuda_runtime.h>
#include <cuda_fp16.h>
#include <math.h>

#define B 4
#define C 64
#define IC 16
#define H 128
#define W 128
#define N 4096
#define BN_COUNT (B*H*W)
#define SPLITK 4
#define LOG2E 1.44269504088896340736f

// ------------------------- scratch -------------------------
__device__ __half g_qh[B * N * IC];        // Q (theta * log2e)  [n][d]
__device__ __half g_kh[B * N * IC];        // K (phi)            [n][d]
__device__ __half g_vth[B * IC * N];       // V transposed       [b][d][n]
__device__ float g_opart[SPLITK * B * N * IC];
__device__ float g_lpart[SPLITK * B * N];
__device__ float g_mpart[SPLITK * B * N];
__device__ float g_y[B * N * IC];
__device__ float g_z[B * C * H * W];
__device__ float g_bnpart[B * C * 4 * 2];

__device__ __forceinline__ float ex2a(float f) {
    float r; asm("ex2.approx.ftz.f32 %0,%1;" : "=f"(r) : "f"(f)); return r;
}
__device__ __forceinline__ unsigned pack2(float a, float b) {
    __half2 h = __floats2half2_rn(a, b);
    return *(unsigned*)&h;
}
__device__ __forceinline__ void mma_f16(float* d, unsigned a0, unsigned a1, unsigned a2, unsigned a3,
                                        unsigned b0, unsigned b1) {
    asm("mma.sync.aligned.m16n8k16.row.col.f32.f16.f16.f32 "
        "{%0,%1,%2,%3},{%4,%5,%6,%7},{%8,%9},{%0,%1,%2,%3};"
        : "+f"(d[0]), "+f"(d[1]), "+f"(d[2]), "+f"(d[3])
        : "r"(a0), "r"(a1), "r"(a2), "r"(a3), "r"(b0), "r"(b1));
}
__device__ __forceinline__ void mma_f16_zc(float* d, unsigned a0, unsigned a1, unsigned a2, unsigned a3,
                                           unsigned b0, unsigned b1) {
    asm("mma.sync.aligned.m16n8k16.row.col.f32.f16.f16.f32 "
        "{%0,%1,%2,%3},{%4,%5,%6,%7},{%8,%9},{%10,%11,%12,%13};"
        : "=f"(d[0]), "=f"(d[1]), "=f"(d[2]), "=f"(d[3])
        : "r"(a0), "r"(a1), "r"(a2), "r"(a3), "r"(b0), "r"(b1),
          "f"(0.f), "f"(0.f), "f"(0.f), "f"(0.f));
}

// ------------------- K1: downsample (odd-pixel subsample) + QKV (fp16 out) -------------------
// jax scale_and_translate, scale=0.5, trans=-0.25 => sample_f = 2*o+1 (exact hit)
__global__ void __launch_bounds__(256) k_down_proj(
    const float* __restrict__ x,
    const float* __restrict__ gw,  const float* __restrict__ gb,
    const float* __restrict__ thw, const float* __restrict__ thb,
    const float* __restrict__ phw, const float* __restrict__ phb)
{
    __shared__ float xd[64][68];
    __shared__ float Wm[48][64];
    __shared__ float Bm[48];
    __shared__ __half qks[2][64][16];

    int b  = blockIdx.x >> 6;
    int oi = blockIdx.x & 63;
    int t  = threadIdx.x;  // 256

    for (int idx = t; idx < 16 * 64; idx += 256) {
        Wm[idx >> 6][idx & 63]        = thw[idx] * LOG2E;
        Wm[16 + (idx >> 6)][idx & 63] = phw[idx];
        Wm[32 + (idx >> 6)][idx & 63] = gw[idx];
    }
    if (t < 16) { Bm[t] = thb[t] * LOG2E; Bm[16 + t] = phb[t]; Bm[32 + t] = gb[t]; }

    for (int idx = t; idx < 4096; idx += 256) {
        int c = idx >> 6, p = idx & 63;
        xd[p][c] = x[(((size_t)b * C + c) * H + 2 * oi + 1) * W + 2 * p + 1];
    }
    __syncthreads();

    int p   = t & 63;
    int grp = t >> 6;

    float xv[64];
    #pragma unroll
    for (int k = 0; k < 16; k++) *(float4*)&xv[4 * k] = *(float4*)&xd[p][4 * k];

    int base_n = b * N + oi * 64;
    #pragma unroll
    for (int j = 0; j < 12; j++) {
        int o = grp * 12 + j;
        float s0 = 0.f, s1 = 0.f, s2 = 0.f, s3 = 0.f;
        #pragma unroll
        for (int k = 0; k < 16; k++) {
            float4 wv = *(float4*)&Wm[o][4 * k];
            s0 += wv.x * xv[4 * k];
            s1 += wv.y * xv[4 * k + 1];
            s2 += wv.z * xv[4 * k + 2];
            s3 += wv.w * xv[4 * k + 3];
        }
        float s = Bm[o] + ((s0 + s1) + (s2 + s3));
        int which = o >> 4, oo = o & 15;
        if (which < 2) qks[which][p][oo] = __float2half_rn(s);
        else           g_vth[((size_t)b * IC + oo) * N + oi * 64 + p] = __float2half_rn(s);
    }
    __syncthreads();

    for (int idx = t; idx < 1024; idx += 256) {
        int which = idx >> 9;
        int rest  = idx & 511;
        int pp = rest >> 3, u = rest & 7;
        unsigned v = *(unsigned*)&qks[which][pp][u * 2];
        __half* dst = which ? g_kh : g_qh;
        *((unsigned*)dst + (size_t)(base_n + pp) * 8 + u) = v;
    }
}

// ------------------- K2: fp16 mma flash attention, KT=64, double-buffered -------------------
#define KT 64
#define KPC (N / SPLITK)
#define NTILES (KPC / KT)
__global__ void __launch_bounds__(128) k_attn()
{
    __shared__ __half Ks[KT][24];    // [key][d] pad 24 halves -> conflict-free B-frag
    __shared__ __half Vt[24][72];    // [d][key] pad 72 halves -> conflict-free B-frag

    int b    = blockIdx.x >> 8;
    int qt   = (blockIdx.x >> 2) & 63;
    int part = blockIdx.x & 3;
    int t    = threadIdx.x;
    int wp   = t >> 5;
    int lane = t & 31;
    int g    = lane >> 2;
    int t4   = lane & 3;

    int q0 = b * N + qt * 64 + wp * 16;

    unsigned qa0 = *(const unsigned*)(g_qh + (size_t)(q0 + g)     * IC + 2 * t4);
    unsigned qa1 = *(const unsigned*)(g_qh + (size_t)(q0 + g + 8) * IC + 2 * t4);
    unsigned qa2 = *(const unsigned*)(g_qh + (size_t)(q0 + g)     * IC + 2 * t4 + 8);
    unsigned qa3 = *(const unsigned*)(g_qh + (size_t)(q0 + g + 8) * IC + 2 * t4 + 8);

    float od[3][4];
    #pragma unroll
    for (int c = 0; c < 3; c++)
        #pragma unroll
        for (int i = 0; i < 4; i++) od[c][i] = 0.f;
    float m0 = -1e30f, m1 = -1e30f;

    // init Vt ones region rows 16..23 (row 16 = 1, rest 0)
    for (int idx = t; idx < 8 * 72; idx += 128) {
        int r = idx / 72, cc = idx - r * 72;
        Vt[16 + r][cc] = (r == 0) ? __float2half(1.f) : __float2half(0.f);
    }

    int koff = b * N + part * KPC;
    // per-thread load coords: K tile 64x16 halves = 2KB -> one uint4/thread
    int krow = t >> 1, kseg = (t & 1) * 8;       // Ks[krow][kseg..kseg+7]
    int vrow = t >> 3, vseg = (t & 7) * 8;       // Vt[vrow][vseg..vseg+7]

    uint4 kreg = *(const uint4*)(g_kh + (size_t)(koff + krow) * IC + kseg);
    uint4 vreg = *(const uint4*)(g_vth + ((size_t)b * IC + vrow) * N + part * KPC + vseg);

    for (int it = 0; it < NTILES; it++) {
        *(uint4*)&Ks[krow][kseg] = kreg;
        *(uint4*)&Vt[vrow][vseg] = vreg;
        __syncthreads();

        if (it + 1 < NTILES) {
            int nk = koff + (it + 1) * KT;
            kreg = *(const uint4*)(g_kh + (size_t)(nk + krow) * IC + kseg);
            vreg = *(const uint4*)(g_vth + ((size_t)b * IC + vrow) * N + part * KPC + (it + 1) * KT + vseg);
        }

        // S = Q K^T : 8 key-chunks of 8
        float p[8][4];
        #pragma unroll
        for (int c = 0; c < 8; c++) {
            unsigned kb0 = *(const unsigned*)&Ks[c * 8 + g][2 * t4];
            unsigned kb1 = *(const unsigned*)&Ks[c * 8 + g][2 * t4 + 8];
            mma_f16_zc(p[c], qa0, qa1, qa2, qa3, kb0, kb1);
        }

        // tile max per row
        float tm0 = -1e30f, tm1 = -1e30f;
        #pragma unroll
        for (int c = 0; c < 8; c++) {
            tm0 = fmaxf(tm0, fmaxf(p[c][0], p[c][1]));
            tm1 = fmaxf(tm1, fmaxf(p[c][2], p[c][3]));
        }
        tm0 = fmaxf(tm0, __shfl_xor_sync(0xffffffffu, tm0, 1));
        tm0 = fmaxf(tm0, __shfl_xor_sync(0xffffffffu, tm0, 2));
        tm1 = fmaxf(tm1, __shfl_xor_sync(0xffffffffu, tm1, 1));
        tm1 = fmaxf(tm1, __shfl_xor_sync(0xffffffffu, tm1, 2));

        bool need = (tm0 > m0) || (tm1 > m1);
        if (__any_sync(0xffffffffu, need)) {
            float mn0 = fmaxf(m0, tm0), mn1 = fmaxf(m1, tm1);
            float f0 = ex2a(m0 - mn0), f1 = ex2a(m1 - mn1);
            m0 = mn0; m1 = mn1;
            #pragma unroll
            for (int c = 0; c < 3; c++) {
                od[c][0] *= f0; od[c][1] *= f0;
                od[c][2] *= f1; od[c][3] *= f1;
            }
        }

        // p = exp2(s - m), fp16 pairs = PV A-fragments
        unsigned pp0[8], pp1[8];
        #pragma unroll
        for (int c = 0; c < 8; c++) {
            unsigned u0 = pack2(p[c][0] - m0, p[c][1] - m0);
            unsigned u1 = pack2(p[c][2] - m1, p[c][3] - m1);
            __half2 e0 = h2exp2(*(__half2*)&u0);
            __half2 e1 = h2exp2(*(__half2*)&u1);
            pp0[c] = *(unsigned*)&e0;
            pp1[c] = *(unsigned*)&e1;
        }

        // PV (+ ones column -> l): 4 key-steps x 3 n-chunks
        #pragma unroll
        for (int s = 0; s < 4; s++) {
            unsigned a0 = pp0[2 * s], a1 = pp1[2 * s], a2 = pp0[2 * s + 1], a3 = pp1[2 * s + 1];
            #pragma unroll
            for (int nc = 0; nc < 3; nc++) {
                unsigned vb0 = *(const unsigned*)&Vt[nc * 8 + g][s * 16 + 2 * t4];
                unsigned vb1 = *(const unsigned*)&Vt[nc * 8 + g][s * 16 + 2 * t4 + 8];
                mma_f16(od[nc], a0, a1, a2, a3, vb0, vb1);
            }
        }
        __syncthreads();
    }

    if (t4 == 0) {
        size_t base = (size_t)part * (B * N);
        g_lpart[base + q0 + g]     = od[2][0];
        g_lpart[base + q0 + g + 8] = od[2][2];
        g_mpart[base + q0 + g]     = m0;
        g_mpart[base + q0 + g + 8] = m1;
    }

    float* Ob = g_opart + (size_t)part * (B * N) * IC;
    #pragma unroll
    for (int nc = 0; nc < 2; nc++) {
        *(float2*)&Ob[(size_t)(q0 + g)     * IC + nc * 8 + 2 * t4] = make_float2(od[nc][0], od[nc][1]);
        *(float2*)&Ob[(size_t)(q0 + g + 8) * IC + nc * 8 + 2 * t4] = make_float2(od[nc][2], od[nc][3]);
    }
}

// ------------------- K2b: merge split-K partials (max rescale) -------------------
__global__ void k_merge()
{
    int n = blockIdx.x * 256 + threadIdx.x;
    if (n >= B * N) return;
    float m[SPLITK], sc[SPLITK];
    float M = -1e30f;
    #pragma unroll
    for (int p = 0; p < SPLITK; p++) { m[p] = g_mpart[(size_t)p * (B * N) + n]; M = fmaxf(M, m[p]); }
    float l = 0.f;
    #pragma unroll
    for (int p = 0; p < SPLITK; p++) {
        sc[p] = ex2a(m[p] - M);
        l += g_lpart[(size_t)p * (B * N) + n] * sc[p];
    }
    float inv = 1.f / l;
    float acc[16];
    #pragma unroll
    for (int i = 0; i < 16; i++) acc[i] = 0.f;
    #pragma unroll
    for (int p = 0; p < SPLITK; p++) {
        const float4* a = (const float4*)(g_opart + ((size_t)p * (B * N) + n) * IC);
        #pragma unroll
        for (int i = 0; i < 4; i++) {
            float4 v = a[i];
            acc[i * 4 + 0] += v.x * sc[p]; acc[i * 4 + 1] += v.y * sc[p];
            acc[i * 4 + 2] += v.z * sc[p]; acc[i * 4 + 3] += v.w * sc[p];
        }
    }
    float4* y = (float4*)(g_y + (size_t)n * IC);
    #pragma unroll
    for (int i = 0; i < 4; i++) {
        float4 r;
        r.x = acc[i * 4 + 0] * inv; r.y = acc[i * 4 + 1] * inv;
        r.z = acc[i * 4 + 2] * inv; r.w = acc[i * 4 + 3] * inv;
        y[i] = r;
    }
}

// ------------------- K3: upsample + out conv + residual (512 threads, 16 ch/thread) -------------------
// jax scale_and_translate, scale=2, trans=+0.5 => sample_f = 0.5*o - 0.5 (clamped taps)
__global__ void __launch_bounds__(512) k_out(const float* __restrict__ x,
                                             const float* __restrict__ ow,
                                             const float* __restrict__ ob)
{
    __shared__ float yr[16][65];
    __shared__ float Wo[64][16];
    __shared__ float obs[64];

    int b = blockIdx.x >> 7;
    int h = blockIdx.x & 127;
    int t = threadIdx.x;  // 512

    for (int idx = t; idx < 1024; idx += 512) Wo[idx >> 4][idx & 15] = ow[idx];
    if (t < 64) obs[t] = ob[t];

    float fh = 0.5f * (float)h - 0.5f;
    int   ihf = (int)floorf(fh);
    float w1  = fh - (float)ihf;
    int ih0 = ihf < 0 ? 0 : ihf;
    int ih1 = (ihf + 1) > 63 ? 63 : (ihf + 1);

    for (int idx = t; idx < 1024; idx += 512) {
        int i = idx & 15, jw = idx >> 4;
        float a = g_y[((size_t)b * N + ih0 * 64 + jw) * IC + i];
        float c = g_y[((size_t)b * N + ih1 * 64 + jw) * IC + i];
        yr[i][jw] = (1.f - w1) * a + w1 * c;
    }
    __syncthreads();

    int w  = t & 127;
    int cg = t >> 7;   // 0..3 -> channels cg*16 .. cg*16+15

    float fw = 0.5f * (float)w - 0.5f;
    int   jf = (int)floorf(fw);
    float ww = fw - (float)jf;
    int j0 = jf < 0 ? 0 : jf;
    int j1 = (jf + 1) > 63 ? 63 : (jf + 1);

    float yv[16];
    #pragma unroll
    for (int i = 0; i < 16; i++)
        yv[i] = (1.f - ww) * yr[i][j0] + ww * yr[i][j1];

    const float* xrow = x   + ((size_t)b * C * H + h) * W;
    float*       zrow = g_z + ((size_t)b * C * H + h) * W;

    #pragma unroll
    for (int ci = 0; ci < 16; ci++) {
        int c = cg * 16 + ci;
        float4 w0 = *(float4*)&Wo[c][0];
        float4 w4 = *(float4*)&Wo[c][4];
        float4 w8 = *(float4*)&Wo[c][8];
        float4 wc = *(float4*)&Wo[c][12];
        float s = obs[c];
        s += w0.x * yv[0]  + w0.y * yv[1]  + w0.z * yv[2]  + w0.w * yv[3];
        s += w4.x * yv[4]  + w4.y * yv[5]  + w4.z * yv[6]  + w4.w * yv[7];
        s += w8.x * yv[8]  + w8.y * yv[9]  + w8.z * yv[10] + w8.w * yv[11];
        s += wc.x * yv[12] + wc.y * yv[13] + wc.z * yv[14] + wc.w * yv[15];
        zrow[(size_t)c * (H * W) + w] = xrow[(size_t)c * (H * W) + w] + s;
    }
}

// ------------------- K3b: BN partial reduction over g_z (deterministic) -------------------
__global__ void k_bnred()
{
    __shared__ float ss[8], sq[8];
    int plane = blockIdx.x >> 2;
    int chunk = blockIdx.x & 3;
    int t = threadIdx.x;

    const float4* p = (const float4*)(g_z + (size_t)plane * (H * W) + chunk * 4096);
    float s = 0.f, q = 0.f;
    #pragma unroll
    for (int i = 0; i < 4; i++) {
        float4 v = p[i * 256 + t];
        s += ((v.x + v.y) + (v.z + v.w));
        q += ((v.x * v.x + v.y * v.y) + (v.z * v.z + v.w * v.w));
    }
    #pragma unroll
    for (int off = 16; off; off >>= 1) {
        s += __shfl_down_sync(0xffffffffu, s, off);
        q += __shfl_down_sync(0xffffffffu, q, off);
    }
    int warp = t >> 5, lane = t & 31;
    if (lane == 0) { ss[warp] = s; sq[warp] = q; }
    __syncthreads();
    if (t == 0) {
        float S = ((ss[0] + ss[1]) + (ss[2] + ss[3])) + ((ss[4] + ss[5]) + (ss[6] + ss[7]));
        float Q = ((sq[0] + sq[1]) + (sq[2] + sq[3])) + ((sq[4] + sq[5]) + (sq[6] + sq[7]));
        g_bnpart[((size_t)plane * 4 + chunk) * 2 + 0] = S;
        g_bnpart[((size_t)plane * 4 + chunk) * 2 + 1] = Q;
    }
}

// ------------------- K5: finalize stats (per-CTA, uniform) + normalize -------------------
__global__ void k_norm(const float* __restrict__ gamma, const float* __restrict__ beta,
                       float* __restrict__ out)
{
    size_t i4 = (size_t)blockIdx.x * 256 + threadIdx.x;
    int c = (int)((i4 >> 12) & 63);    // channel constant per CTA

    float s = 0.f, q = 0.f;
    #pragma unroll
    for (int b = 0; b < B; b++)
        #pragma unroll
        for (int ch = 0; ch < 4; ch++) {
            size_t idx = (((size_t)b * C + c) * 4 + ch) * 2;
            s += g_bnpart[idx + 0];
            q += g_bnpart[idx + 1];
        }
    float mean = s * (1.f / (float)BN_COUNT);
    float var  = q * (1.f / (float)BN_COUNT) - mean * mean;
    float rstd = rsqrtf(var + 1e-5f);

    float ga = gamma[c] * rstd;
    float be = beta[c] - mean * ga;
    float4 z = ((const float4*)g_z)[i4];
    float4 r;
    r.x = z.x * ga + be; r.y = z.y * ga + be;
    r.z = z.z * ga + be; r.w = z.w * ga + be;
    ((float4*)out)[i4] = r;
}

// ------------------------------- launch -------------------------------
extern "C" void kernel_launch(void* const* d_in, const int* in_sizes, int n_in,
                              void* d_out, int out_size)
{
    const float* x     = (const float*)d_in[0];
    const float* g_w   = (const float*)d_in[1];
    const float* g_b   = (const float*)d_in[2];
    const float* th_w  = (const float*)d_in[3];
    const float* th_b  = (const float*)d_in[4];
    const float* ph_w  = (const float*)d_in[5];
    const float* ph_b  = (const float*)d_in[6];
    const float* out_w = (const float*)d_in[7];
    const float* out_b = (const float*)d_in[8];
    const float* gamma = (const float*)d_in[9];
    const float* beta  = (const float*)d_in[10];
    float* out = (float*)d_out;

    k_down_proj<<<B * 64, 256>>>(x, g_w, g_b, th_w, th_b, ph_w, ph_b);
    k_attn<<<B * 64 * SPLITK, 128>>>();
    k_merge<<<64, 256>>>();
    k_out<<<B * H, 512>>>(x, out_w, out_b);
    k_bnred<<<B * C * 4, 256>>>();
    k_norm<<<4096, 256>>>(gamma, beta, out);
}